// round 4
// baseline (speedup 1.0000x reference)
#include <cuda_runtime.h>

#define SQ   1024
#define DH   64
#define NBH  32

__device__ float g_partial[16 * NBH * SQ];  // [kblk(16)][bh*SQ + row]
__device__ float g_rinv[NBH * SQ];

// ---------------------------------------------------------------------------
// Kernel 1: E = exp(QK^T/8 + ia_type + ia_feat), mask->0, into attn region.
// Tile 128q x 64k, 256 threads, 8x4 register GEMM, acc staged through smem,
// coalesced float4 epilogue (half-warp per row) with shuffle row sums.
// __launch_bounds__(256,3): 3 blocks/SM so GEMM/epilogue phases overlap.
// ---------------------------------------------------------------------------
__global__ __launch_bounds__(256, 3) void k_scores(
    const float* __restrict__ Q, const float* __restrict__ K,
    const float* __restrict__ iat, const float* __restrict__ iaf,
    const unsigned int* __restrict__ mask, float* __restrict__ E)
{
    const int kb = blockIdx.x;   // 0..15  (64-wide k tile)
    const int qb = blockIdx.y;   // 0..7
    const int bh = blockIdx.z;   // 0..31

    extern __shared__ float sm[];
    float* Qs = sm;                    // 128 x 68
    float* Ks = sm + 128 * 68;         // 64 x 68

    const int tid  = threadIdx.x;
    const int tx   = tid & 15;
    const int ty   = tid >> 4;
    const int lane = tid & 31;
    const int w    = tid >> 5;

    const float* Qg = Q + ((size_t)bh * SQ + (size_t)qb * 128) * DH;
    const float* Kg = K + ((size_t)bh * SQ + (size_t)kb * 64) * DH;

#pragma unroll
    for (int it = 0; it < 8; it++) {
        int f4  = tid + it * 256;
        int row = f4 >> 4;
        int c4  = (f4 & 15) << 2;
        *(float4*)(Qs + row * 68 + c4) = *(const float4*)(Qg + row * DH + c4);
    }
#pragma unroll
    for (int it = 0; it < 4; it++) {
        int f4  = tid + it * 256;
        int row = f4 >> 4;
        int c4  = (f4 & 15) << 2;
        *(float4*)(Ks + row * 68 + c4) = *(const float4*)(Kg + row * DH + c4);
    }
    __syncthreads();

    float acc[8][4];
#pragma unroll
    for (int i = 0; i < 8; i++)
#pragma unroll
        for (int j = 0; j < 4; j++) acc[i][j] = 0.f;

#pragma unroll 4
    for (int d = 0; d < DH; d++) {
        float qv[8], kv[4];
#pragma unroll
        for (int i = 0; i < 8; i++) qv[i] = Qs[(ty + i * 16) * 68 + d];
#pragma unroll
        for (int j = 0; j < 4; j++) kv[j] = Ks[(tx + j * 16) * 68 + d];
#pragma unroll
        for (int i = 0; i < 8; i++)
#pragma unroll
            for (int j = 0; j < 4; j++)
                acc[i][j] = fmaf(qv[i], kv[j], acc[i][j]);
    }
    __syncthreads();

    // Stage accumulators (reuse smem). 128 x 68, stride mult of 4.
    float* Ss = sm;
#pragma unroll
    for (int i = 0; i < 8; i++)
#pragma unroll
        for (int j = 0; j < 4; j++)
            Ss[(ty + i * 16) * 68 + tx + j * 16] = acc[i][j];
    __syncthreads();

    // Epilogue: half-warp per 64-wide row; 16 rows per iteration.
    const int half = lane >> 4;          // 0/1
    const int c    = (lane & 15) << 2;   // 0..60
    const size_t base = (((size_t)bh * SQ) + (size_t)qb * 128) * SQ
                      + (size_t)kb * 64;
#pragma unroll
    for (int it = 0; it < 8; it++) {
        const int row = it * 16 + w * 2 + half;
        const size_t g = base + (size_t)row * SQ + c;
        float4 a  = *(const float4*)(iat + g);
        float4 b  = *(const float4*)(iaf + g);
        uint4  m  = *(const uint4*)(mask + g);
        float4 sv = *(const float4*)(Ss + row * 68 + c);
        float4 e;
        e.x = m.x ? 0.f : __expf(fmaf(sv.x, 0.125f, a.x + b.x));
        e.y = m.y ? 0.f : __expf(fmaf(sv.y, 0.125f, a.y + b.y));
        e.z = m.z ? 0.f : __expf(fmaf(sv.z, 0.125f, a.z + b.z));
        e.w = m.w ? 0.f : __expf(fmaf(sv.w, 0.125f, a.w + b.w));
        *(float4*)(E + g) = e;

        float part = (e.x + e.y) + (e.z + e.w);
#pragma unroll
        for (int o = 8; o > 0; o >>= 1)
            part += __shfl_xor_sync(0xffffffffu, part, o);
        if ((lane & 15) == 0)
            g_partial[(size_t)kb * (NBH * SQ) + (size_t)bh * SQ
                      + (size_t)qb * 128 + row] = part;
    }
}

// ---------------------------------------------------------------------------
__global__ __launch_bounds__(256) void k_rowsum()
{
    const int r = blockIdx.x * 256 + threadIdx.x;
    float s = 0.f;
#pragma unroll
    for (int kb = 0; kb < 16; kb++) s += g_partial[kb * (NBH * SQ) + r];
    g_rinv[r] = 1.f / s;
}

// ---------------------------------------------------------------------------
// Kernel 2: normalize attn in place + context = rinv * (E @ V).
// Tile 64q x 64d, k-tiles of 128, 256 threads, 4x4 blocking with float4 V
// loads. smem ~69KB, regs ~50 -> 3 blocks/SM.
// ---------------------------------------------------------------------------
__global__ __launch_bounds__(256, 3) void k_pv(
    const float* __restrict__ V, float* __restrict__ attn,
    float* __restrict__ ctx)
{
    const int qb = blockIdx.x;   // 0..15 (64-row q tile)
    const int bh = blockIdx.y;   // 0..31

    extern __shared__ float sm[];
    float* Es  = sm;                               // 64 x 132
    float* Vs  = sm + 64 * 132;                    // 128 x 68
    float* sRi = sm + 64 * 132 + 128 * 68;         // 64

    const int tid  = threadIdx.x;
    const int tx   = tid & 15;   // col group: cols tx*4 + j
    const int ty   = tid >> 4;   // row group: rows ty*4 + i
    const int lane = tid & 31;
    const int w    = tid >> 5;

    if (tid < 64)
        sRi[tid] = g_rinv[(size_t)bh * SQ + (size_t)qb * 64 + tid];
    __syncthreads();

    float acc[4][4];
#pragma unroll
    for (int i = 0; i < 4; i++)
#pragma unroll
        for (int j = 0; j < 4; j++) acc[i][j] = 0.f;

    for (int kt = 0; kt < 8; kt++) {
        __syncthreads();
        const size_t ebase = (((size_t)bh * SQ) + (size_t)qb * 64) * SQ
                           + (size_t)kt * 128;
        // E tile 64x128: one warp per row (32 lanes x float4 = 128 floats).
        // Fused normalized write-back.
#pragma unroll
        for (int it = 0; it < 8; it++) {
            const int row = it * 8 + w;
            const int c   = lane << 2;
            const size_t g = ebase + (size_t)row * SQ + c;
            float4 v = *(const float4*)(attn + g);
            *(float4*)(Es + row * 132 + c) = v;
            const float rv = sRi[row];
            v.x *= rv; v.y *= rv; v.z *= rv; v.w *= rv;
            *(float4*)(attn + g) = v;
        }
        // V tile 128x64
        const float* Vg = V + ((size_t)bh * SQ + (size_t)kt * 128) * DH;
#pragma unroll
        for (int it = 0; it < 8; it++) {
            int f4  = tid + it * 256;
            int row = f4 >> 4;
            int c4  = (f4 & 15) << 2;
            *(float4*)(Vs + row * 68 + c4) = *(const float4*)(Vg + row * DH + c4);
        }
        __syncthreads();

#pragma unroll 4
        for (int k = 0; k < 128; k++) {
            float ev[4];
#pragma unroll
            for (int i = 0; i < 4; i++) ev[i] = Es[(ty * 4 + i) * 132 + k];
            float4 vv = *(const float4*)(Vs + k * 68 + tx * 4);
#pragma unroll
            for (int i = 0; i < 4; i++) {
                acc[i][0] = fmaf(ev[i], vv.x, acc[i][0]);
                acc[i][1] = fmaf(ev[i], vv.y, acc[i][1]);
                acc[i][2] = fmaf(ev[i], vv.z, acc[i][2]);
                acc[i][3] = fmaf(ev[i], vv.w, acc[i][3]);
            }
        }
    }

    // Epilogue: float4 context stores
#pragma unroll
    for (int i = 0; i < 4; i++) {
        const int r = ty * 4 + i;
        const float rv = sRi[r];
        const size_t ob = (((size_t)bh * SQ) + (size_t)qb * 64 + r) * DH;
        float4 o;
        o.x = acc[i][0] * rv;
        o.y = acc[i][1] * rv;
        o.z = acc[i][2] * rv;
        o.w = acc[i][3] * rv;
        *(float4*)(ctx + ob + tx * 4) = o;
    }
}

// ---------------------------------------------------------------------------
extern "C" void kernel_launch(void* const* d_in, const int* in_sizes, int n_in,
                              void* d_out, int out_size)
{
    const float*        Q    = (const float*)d_in[0];
    const float*        K    = (const float*)d_in[1];
    const float*        V    = (const float*)d_in[2];
    const unsigned int* mask = (const unsigned int*)d_in[4];  // attn_mask_if
    const float*        iat  = (const float*)d_in[5];
    const float*        iaf  = (const float*)d_in[6];

    float* ctx  = (float*)d_out;
    float* attn = ctx + (size_t)NBH * SQ * DH;

    const int smem1 = (128 * 68 + 64 * 68) * 4;                 // 52224 B
    const int smem2 = (64 * 132 + 128 * 68 + 64) * 4;           // 68864 B
    cudaFuncSetAttribute(k_scores, cudaFuncAttributeMaxDynamicSharedMemorySize, smem1);
    cudaFuncSetAttribute(k_pv,     cudaFuncAttributeMaxDynamicSharedMemorySize, smem2);

    dim3 g1(16, 8, NBH);
    k_scores<<<g1, 256, smem1>>>(Q, K, iat, iaf, mask, attn);

    k_rowsum<<<(NBH * SQ) / 256, 256>>>();

    dim3 g2(16, NBH);
    k_pv<<<g2, 256, smem2>>>(V, attn, ctx);
}